// round 12
// baseline (speedup 1.0000x reference)
#include <cuda_runtime.h>

#define NN 1024
#define HH 128
#define NJB 8           // j-blocks of 128

// Device-global scratch (no allocation allowed)
__device__ float g_part[NJB * NN * HH];   // per-jblock partial aggregates
__device__ float g_gi[NN * 3 * HH];       // gi = agg @ w_ih^T   [1024][384]
__device__ float g_gh[NN * 3 * HH];       // gh = nf  @ w_hh^T   [1024][384]

// ---------------------------------------------------------------------------
// Kernel 1: barrier-free partial aggregation (round-9, measured 60.2us at
// its ~4.6 TB/s gated-scatter DRAM floor; regs 32, no smem, occ 73%).
// grid (128, 8) blocks of 256; warp w owns row i = ib*8+w.
// ---------------------------------------------------------------------------
__global__ __launch_bounds__(256) void agg_kernel(
    const float* __restrict__ nf,
    const int*   __restrict__ adj,
    const float* __restrict__ T)
{
    const int ib   = blockIdx.x;
    const int jb   = blockIdx.y;
    const int tid  = threadIdx.x;
    const int lane = tid & 31;
    const int w    = tid >> 5;
    const int i    = ib * 8 + w;

    const float4* nf4 = (const float4*)nf;
    const float4* T4  = (const float4*)T;

    float4 a0 = make_float4(0.f,0.f,0.f,0.f);
    float4 a1 = make_float4(0.f,0.f,0.f,0.f);
    float4 a2 = make_float4(0.f,0.f,0.f,0.f);
    float4 a3 = make_float4(0.f,0.f,0.f,0.f);

    const int* adjrow = adj + (size_t)i * NN + jb * 128;

    #pragma unroll 1
    for (int c = 0; c < 4; c++) {
        const int av = __ldg(&adjrow[c * 32 + lane]);
        unsigned m = __ballot_sync(0xffffffffu, av != 0);
        int tot = __popc(m);

        const int    jbase   = jb * 128 + c * 32;
        const size_t rowbase = (size_t)i * NN + jbase;

        while (tot >= 4) {
            const int j0 = __ffs(m) - 1; m &= m - 1;
            const int j1 = __ffs(m) - 1; m &= m - 1;
            const int j2 = __ffs(m) - 1; m &= m - 1;
            const int j3 = __ffs(m) - 1; m &= m - 1;
            tot -= 4;
            float4 t0 = __ldcs(&T4[(rowbase + j0) * 32 + lane]);
            float4 t1 = __ldcs(&T4[(rowbase + j1) * 32 + lane]);
            float4 t2 = __ldcs(&T4[(rowbase + j2) * 32 + lane]);
            float4 t3 = __ldcs(&T4[(rowbase + j3) * 32 + lane]);
            float4 f0 = __ldg(&nf4[(size_t)(jbase + j0) * 32 + lane]);
            float4 f1 = __ldg(&nf4[(size_t)(jbase + j1) * 32 + lane]);
            float4 f2 = __ldg(&nf4[(size_t)(jbase + j2) * 32 + lane]);
            float4 f3 = __ldg(&nf4[(size_t)(jbase + j3) * 32 + lane]);
            a0.x += f0.x*t0.x; a0.y += f0.y*t0.y; a0.z += f0.z*t0.z; a0.w += f0.w*t0.w;
            a1.x += f1.x*t1.x; a1.y += f1.y*t1.y; a1.z += f1.z*t1.z; a1.w += f1.w*t1.w;
            a2.x += f2.x*t2.x; a2.y += f2.y*t2.y; a2.z += f2.z*t2.z; a2.w += f2.w*t2.w;
            a3.x += f3.x*t3.x; a3.y += f3.y*t3.y; a3.z += f3.z*t3.z; a3.w += f3.w*t3.w;
        }
        while (tot > 0) {
            const int j = __ffs(m) - 1; m &= m - 1; tot--;
            float4 t = __ldcs(&T4[(rowbase + j) * 32 + lane]);
            float4 f = __ldg(&nf4[(size_t)(jbase + j) * 32 + lane]);
            a0.x += f.x*t.x; a0.y += f.y*t.y; a0.z += f.z*t.z; a0.w += f.w*t.w;
        }
    }

    a0.x += a1.x + a2.x + a3.x;
    a0.y += a1.y + a2.y + a3.y;
    a0.z += a1.z + a2.z + a3.z;
    a0.w += a1.w + a2.w + a3.w;

    ((float4*)g_part)[((size_t)jb * NN + i) * 32 + lane] = a0;
}

// ---------------------------------------------------------------------------
// Kernel 2: tiled GEMM  C[1024 x 384] = A[1024 x 128] @ W[384 x 128]^T.
// 32x64 tiles, 2x4 microtile -> ~40 regs, 14 KB smem -> ~6 CTAs/SM.
// grid (32 mtiles, 6 ntiles, 2): z=0 -> A=sum(g_part), W=wih, C=g_gi
//                                z=1 -> A=nf,          W=whh, C=g_gh
// ---------------------------------------------------------------------------
__global__ __launch_bounds__(256) void gemm_kernel(
    const float* __restrict__ nf,
    const float* __restrict__ wih,
    const float* __restrict__ whh)
{
    const int mt  = blockIdx.x;
    const int nt  = blockIdx.y;
    const int zz  = blockIdx.z;
    const int tid = threadIdx.x;
    const int tx  = tid & 15;              // 4-col group
    const int ty  = tid >> 4;              // 2-row group

    const float4* A4 = (const float4*)nf;
    const float4* P4 = (const float4*)g_part;
    const float4* W4 = (const float4*)(zz ? whh : wih);
    float4*       C4 = (float4*)(zz ? g_gh : g_gi);

    __shared__ float4 sA[32][9];           // padded
    __shared__ float4 sB[64][9];

    const int mbase = mt * 32;
    const int nbase = nt * 64;

    float c00=0,c01=0,c02=0,c03=0, c10=0,c11=0,c12=0,c13=0;

    #pragma unroll
    for (int kb = 0; kb < 4; kb++) {
        {   // stage A: 256 f4, one per thread (inline 8-slab sum for gi)
            const int m = tid >> 3, kq = tid & 7;
            const size_t gidx = (size_t)(mbase + m) * 32 + kb * 8 + kq;
            float4 s;
            if (zz) {
                s = A4[gidx];
            } else {
                s = P4[gidx];
                #pragma unroll
                for (int p = 1; p < NJB; p++) {
                    float4 v = P4[(size_t)p * (NN * 32) + gidx];
                    s.x += v.x; s.y += v.y; s.z += v.z; s.w += v.w;
                }
            }
            sA[m][kq] = s;
        }
        #pragma unroll
        for (int e = tid; e < 64 * 8; e += 256) {   // stage B: 512 f4
            const int n = e >> 3, kq = e & 7;
            sB[n][kq] = W4[(size_t)(nbase + n) * 32 + kb * 8 + kq];
        }
        __syncthreads();

        #pragma unroll
        for (int kq = 0; kq < 8; kq++) {
            const float4 a0 = sA[ty * 2 + 0][kq];
            const float4 a1 = sA[ty * 2 + 1][kq];
            const float4 b0 = sB[tx * 4 + 0][kq];
            const float4 b1 = sB[tx * 4 + 1][kq];
            const float4 b2 = sB[tx * 4 + 2][kq];
            const float4 b3 = sB[tx * 4 + 3][kq];
            c00 += a0.x*b0.x + a0.y*b0.y + a0.z*b0.z + a0.w*b0.w;
            c01 += a0.x*b1.x + a0.y*b1.y + a0.z*b1.z + a0.w*b1.w;
            c02 += a0.x*b2.x + a0.y*b2.y + a0.z*b2.z + a0.w*b2.w;
            c03 += a0.x*b3.x + a0.y*b3.y + a0.z*b3.z + a0.w*b3.w;
            c10 += a1.x*b0.x + a1.y*b0.y + a1.z*b0.z + a1.w*b0.w;
            c11 += a1.x*b1.x + a1.y*b1.y + a1.z*b1.z + a1.w*b1.w;
            c12 += a1.x*b2.x + a1.y*b2.y + a1.z*b2.z + a1.w*b2.w;
            c13 += a1.x*b3.x + a1.y*b3.y + a1.z*b3.z + a1.w*b3.w;
        }
        __syncthreads();
    }

    const int m0 = mbase + ty * 2;
    const int n4 = nt * 16 + tx;
    C4[(size_t)(m0 + 0) * 96 + n4] = make_float4(c00, c01, c02, c03);
    C4[(size_t)(m0 + 1) * 96 + n4] = make_float4(c10, c11, c12, c13);
}

// ---------------------------------------------------------------------------
// Kernel 3: fused GRU epilogue. One thread per (i,h).
// ---------------------------------------------------------------------------
__global__ __launch_bounds__(256) void gru_ep_kernel(
    const float* __restrict__ nf,
    const float* __restrict__ bih,
    const float* __restrict__ bhh,
    float*       __restrict__ out)
{
    const int idx = blockIdx.x * 256 + threadIdx.x;   // i*128 + h
    const int i = idx >> 7;
    const int h = idx & 127;
    const size_t base = (size_t)i * 384 + h;

    const float r = 1.f / (1.f + __expf(-(g_gi[base] + g_gh[base]
                                          + bih[h] + bhh[h])));
    const float z = 1.f / (1.f + __expf(-(g_gi[base + 128] + g_gh[base + 128]
                                          + bih[h + 128] + bhh[h + 128])));
    const float n = tanhf(g_gi[base + 256] + bih[h + 256]
                          + r * (g_gh[base + 256] + bhh[h + 256]));
    out[idx] = (1.f - z) * n + z * nf[idx];
}

extern "C" void kernel_launch(void* const* d_in, const int* in_sizes, int n_in,
                              void* d_out, int out_size)
{
    const float* nf  = (const float*)d_in[0];
    const int*   adj = (const int*)  d_in[1];
    const float* T   = (const float*)d_in[2];
    const float* wih = (const float*)d_in[3];
    const float* whh = (const float*)d_in[4];
    const float* bih = (const float*)d_in[5];
    const float* bhh = (const float*)d_in[6];
    float* out = (float*)d_out;

    agg_kernel<<<dim3(NN / 8, NJB), 256>>>(nf, adj, T);
    gemm_kernel<<<dim3(32, 6, 2), 256>>>(nf, wih, whh);
    gru_ep_kernel<<<(NN * HH) / 256, 256>>>(nf, bih, bhh, out);
}

// round 13
// speedup vs baseline: 1.1312x; 1.1312x over previous
#include <cuda_runtime.h>

#define NN 1024
#define HH 128
#define NJB 8           // j-blocks of 128

// Device-global scratch (no allocation allowed)
__device__ float g_agg[NN * HH];          // atomically accumulated aggregate
__device__ float g_gi[NN * 3 * HH];       // gi = agg @ w_ih^T   [1024][384]
__device__ float g_gh[NN * 3 * HH];       // gh = nf  @ w_hh^T   [1024][384]

// ---------------------------------------------------------------------------
// Kernel 1: barrier-free partial aggregation (round-9 core, measured 60.2us,
// regs 32, occ 73%, at the ~4.6 TB/s gated-scatter DRAM floor).
// Output: atomicAdd into g_agg (replaces the 8-slab g_part round trip; RED
// traffic hides under the DRAM-bound mainloop). g_agg is zeroed by a
// captured memset before this kernel runs.
// ---------------------------------------------------------------------------
__global__ __launch_bounds__(256) void agg_kernel(
    const float* __restrict__ nf,
    const int*   __restrict__ adj,
    const float* __restrict__ T)
{
    const int ib   = blockIdx.x;
    const int jb   = blockIdx.y;
    const int tid  = threadIdx.x;
    const int lane = tid & 31;
    const int w    = tid >> 5;
    const int i    = ib * 8 + w;

    const float4* nf4 = (const float4*)nf;
    const float4* T4  = (const float4*)T;

    float4 a0 = make_float4(0.f,0.f,0.f,0.f);
    float4 a1 = make_float4(0.f,0.f,0.f,0.f);
    float4 a2 = make_float4(0.f,0.f,0.f,0.f);
    float4 a3 = make_float4(0.f,0.f,0.f,0.f);

    const int* adjrow = adj + (size_t)i * NN + jb * 128;

    #pragma unroll 1
    for (int c = 0; c < 4; c++) {
        const int av = __ldg(&adjrow[c * 32 + lane]);
        unsigned m = __ballot_sync(0xffffffffu, av != 0);
        int tot = __popc(m);

        const int    jbase   = jb * 128 + c * 32;
        const size_t rowbase = (size_t)i * NN + jbase;

        while (tot >= 4) {
            const int j0 = __ffs(m) - 1; m &= m - 1;
            const int j1 = __ffs(m) - 1; m &= m - 1;
            const int j2 = __ffs(m) - 1; m &= m - 1;
            const int j3 = __ffs(m) - 1; m &= m - 1;
            tot -= 4;
            float4 t0 = __ldcs(&T4[(rowbase + j0) * 32 + lane]);
            float4 t1 = __ldcs(&T4[(rowbase + j1) * 32 + lane]);
            float4 t2 = __ldcs(&T4[(rowbase + j2) * 32 + lane]);
            float4 t3 = __ldcs(&T4[(rowbase + j3) * 32 + lane]);
            float4 f0 = __ldg(&nf4[(size_t)(jbase + j0) * 32 + lane]);
            float4 f1 = __ldg(&nf4[(size_t)(jbase + j1) * 32 + lane]);
            float4 f2 = __ldg(&nf4[(size_t)(jbase + j2) * 32 + lane]);
            float4 f3 = __ldg(&nf4[(size_t)(jbase + j3) * 32 + lane]);
            a0.x += f0.x*t0.x; a0.y += f0.y*t0.y; a0.z += f0.z*t0.z; a0.w += f0.w*t0.w;
            a1.x += f1.x*t1.x; a1.y += f1.y*t1.y; a1.z += f1.z*t1.z; a1.w += f1.w*t1.w;
            a2.x += f2.x*t2.x; a2.y += f2.y*t2.y; a2.z += f2.z*t2.z; a2.w += f2.w*t2.w;
            a3.x += f3.x*t3.x; a3.y += f3.y*t3.y; a3.z += f3.z*t3.z; a3.w += f3.w*t3.w;
        }
        while (tot > 0) {
            const int j = __ffs(m) - 1; m &= m - 1; tot--;
            float4 t = __ldcs(&T4[(rowbase + j) * 32 + lane]);
            float4 f = __ldg(&nf4[(size_t)(jbase + j) * 32 + lane]);
            a0.x += f.x*t.x; a0.y += f.y*t.y; a0.z += f.z*t.z; a0.w += f.w*t.w;
        }
    }

    a0.x += a1.x + a2.x + a3.x;
    a0.y += a1.y + a2.y + a3.y;
    a0.z += a1.z + a2.z + a3.z;
    a0.w += a1.w + a2.w + a3.w;

    float* dst = g_agg + (size_t)i * HH + lane * 4;
    atomicAdd(dst + 0, a0.x);
    atomicAdd(dst + 1, a0.y);
    atomicAdd(dst + 2, a0.z);
    atomicAdd(dst + 3, a0.w);
}

// ---------------------------------------------------------------------------
// Kernel 2: tiled GEMM  C[1024 x 384] = A[1024 x 128] @ W[384 x 128]^T.
// grid (16, 6), 64x64 tile, 4x4 microtile (the proven round-9 shape).
// Called twice: (nf, whh) -> g_gh   [overlapped with agg on a side stream]
//               (g_agg, wih) -> g_gi [after agg completes]
// ---------------------------------------------------------------------------
__global__ __launch_bounds__(256) void gemm64_kernel(
    const float* __restrict__ A,
    const float* __restrict__ W,
    float*       __restrict__ C)
{
    const int mt  = blockIdx.x;
    const int nt  = blockIdx.y;
    const int tid = threadIdx.x;
    const int tx  = tid & 15;
    const int ty  = tid >> 4;

    const float4* A4 = (const float4*)A;
    const float4* W4 = (const float4*)W;
    float4*       C4 = (float4*)C;

    __shared__ float4 sA[64][17];
    __shared__ float4 sB[64][17];

    const int mbase = mt * 64;
    const int nbase = nt * 64;

    float c00=0,c01=0,c02=0,c03=0, c10=0,c11=0,c12=0,c13=0;
    float c20=0,c21=0,c22=0,c23=0, c30=0,c31=0,c32=0,c33=0;

    #pragma unroll
    for (int kb = 0; kb < 2; kb++) {
        #pragma unroll
        for (int e = tid; e < 64 * 16; e += 256) {
            const int m = e >> 4, kq = e & 15;
            sA[m][kq] = A4[(size_t)(mbase + m) * 32 + kb * 16 + kq];
        }
        #pragma unroll
        for (int e = tid; e < 64 * 16; e += 256) {
            const int n = e >> 4, kq = e & 15;
            sB[n][kq] = W4[(size_t)(nbase + n) * 32 + kb * 16 + kq];
        }
        __syncthreads();

        #pragma unroll
        for (int kq = 0; kq < 16; kq++) {
            const float4 a0 = sA[ty * 4 + 0][kq];
            const float4 a1 = sA[ty * 4 + 1][kq];
            const float4 a2 = sA[ty * 4 + 2][kq];
            const float4 a3 = sA[ty * 4 + 3][kq];
            const float4 b0 = sB[tx * 4 + 0][kq];
            const float4 b1 = sB[tx * 4 + 1][kq];
            const float4 b2 = sB[tx * 4 + 2][kq];
            const float4 b3 = sB[tx * 4 + 3][kq];

            c00 += a0.x*b0.x + a0.y*b0.y + a0.z*b0.z + a0.w*b0.w;
            c01 += a0.x*b1.x + a0.y*b1.y + a0.z*b1.z + a0.w*b1.w;
            c02 += a0.x*b2.x + a0.y*b2.y + a0.z*b2.z + a0.w*b2.w;
            c03 += a0.x*b3.x + a0.y*b3.y + a0.z*b3.z + a0.w*b3.w;
            c10 += a1.x*b0.x + a1.y*b0.y + a1.z*b0.z + a1.w*b0.w;
            c11 += a1.x*b1.x + a1.y*b1.y + a1.z*b1.z + a1.w*b1.w;
            c12 += a1.x*b2.x + a1.y*b2.y + a1.z*b2.z + a1.w*b2.w;
            c13 += a1.x*b3.x + a1.y*b3.y + a1.z*b3.z + a1.w*b3.w;
            c20 += a2.x*b0.x + a2.y*b0.y + a2.z*b0.z + a2.w*b0.w;
            c21 += a2.x*b1.x + a2.y*b1.y + a2.z*b1.z + a2.w*b1.w;
            c22 += a2.x*b2.x + a2.y*b2.y + a2.z*b2.z + a2.w*b2.w;
            c23 += a2.x*b3.x + a2.y*b3.y + a2.z*b3.z + a2.w*b3.w;
            c30 += a3.x*b0.x + a3.y*b0.y + a3.z*b0.z + a3.w*b0.w;
            c31 += a3.x*b1.x + a3.y*b1.y + a3.z*b1.z + a3.w*b1.w;
            c32 += a3.x*b2.x + a3.y*b2.y + a3.z*b2.z + a3.w*b2.w;
            c33 += a3.x*b3.x + a3.y*b3.y + a3.z*b3.z + a3.w*b3.w;
        }
        __syncthreads();
    }

    const int m0 = mbase + ty * 4;
    const int n4 = nt * 16 + tx;
    C4[(size_t)(m0 + 0) * 96 + n4] = make_float4(c00, c01, c02, c03);
    C4[(size_t)(m0 + 1) * 96 + n4] = make_float4(c10, c11, c12, c13);
    C4[(size_t)(m0 + 2) * 96 + n4] = make_float4(c20, c21, c22, c23);
    C4[(size_t)(m0 + 3) * 96 + n4] = make_float4(c30, c31, c32, c33);
}

// ---------------------------------------------------------------------------
// Kernel 3: fused GRU epilogue. One thread per (i,h).
// ---------------------------------------------------------------------------
__global__ __launch_bounds__(256) void gru_ep_kernel(
    const float* __restrict__ nf,
    const float* __restrict__ bih,
    const float* __restrict__ bhh,
    float*       __restrict__ out)
{
    const int idx = blockIdx.x * 256 + threadIdx.x;   // i*128 + h
    const int i = idx >> 7;
    const int h = idx & 127;
    const size_t base = (size_t)i * 384 + h;

    const float r = 1.f / (1.f + __expf(-(g_gi[base] + g_gh[base]
                                          + bih[h] + bhh[h])));
    const float z = 1.f / (1.f + __expf(-(g_gi[base + 128] + g_gh[base + 128]
                                          + bih[h + 128] + bhh[h + 128])));
    const float n = tanhf(g_gi[base + 256] + bih[h + 256]
                          + r * (g_gh[base + 256] + bhh[h + 256]));
    out[idx] = (1.f - z) * n + z * nf[idx];
}

extern "C" void kernel_launch(void* const* d_in, const int* in_sizes, int n_in,
                              void* d_out, int out_size)
{
    const float* nf  = (const float*)d_in[0];
    const int*   adj = (const int*)  d_in[1];
    const float* T   = (const float*)d_in[2];
    const float* wih = (const float*)d_in[3];
    const float* whh = (const float*)d_in[4];
    const float* bih = (const float*)d_in[5];
    const float* bhh = (const float*)d_in[6];
    float* out = (float*)d_out;

    float* agg_ptr = nullptr;
    cudaGetSymbolAddress((void**)&agg_ptr, g_agg);
    float* gi_ptr = nullptr;
    cudaGetSymbolAddress((void**)&gi_ptr, g_gi);
    float* gh_ptr = nullptr;
    cudaGetSymbolAddress((void**)&gh_ptr, g_gh);

    // Fresh fork/join handles each call (host-side only; no device memory).
    cudaStream_t s2;
    cudaEvent_t  ef, ej;
    cudaStreamCreateWithFlags(&s2, cudaStreamNonBlocking);
    cudaEventCreateWithFlags(&ef, cudaEventDisableTiming);
    cudaEventCreateWithFlags(&ej, cudaEventDisableTiming);

    // Main stream: zero the atomic accumulator, then run agg.
    cudaMemsetAsync(agg_ptr, 0, (size_t)NN * HH * sizeof(float), 0);

    // Fork: gh GEMM (independent of agg) runs concurrently on s2.
    cudaEventRecord(ef, 0);
    cudaStreamWaitEvent(s2, ef, 0);
    gemm64_kernel<<<dim3(16, 6), 256, 0, s2>>>(nf, whh, gh_ptr);

    agg_kernel<<<dim3(NN / 8, NJB), 256>>>(nf, adj, T);

    // Join: gi GEMM needs agg (stream 0) ; epilogue needs gh (s2) too.
    cudaEventRecord(ej, s2);
    cudaStreamWaitEvent(0, ej, 0);

    gemm64_kernel<<<dim3(16, 6), 256>>>(agg_ptr, wih, gi_ptr);
    gru_ep_kernel<<<(NN * HH) / 256, 256>>>(nf, bih, bhh, out);
}